// round 12
// baseline (speedup 1.0000x reference)
#include <cuda_runtime.h>
#include <cstdint>

// label: int32 [8,1024,1024]; out: float32 [8,1,64,64]
// 512 CTAs x 256 thr (4/SM). CTA = one band (16 rows x 4KB = 64KB contiguous),
// streamed by TMA cp.async.bulk in 4 chunks of 16KB (4 rows) into a
// double-buffered smem ring (mbarrier expect_tx). Consumers: warp w = row
// (w&3), col-half (w>>2) of each chunk; 4 conflict-free LDS.128 sweeps.
// Byte-field histogram, warp butterfly, cross-warp smem finalize.
#define CTA_THREADS 256

__device__ __forceinline__ unsigned smem_u32(const void* p) {
    return (unsigned)__cvta_generic_to_shared(p);
}

__device__ __forceinline__ void mbar_init(unsigned addr, unsigned cnt) {
    asm volatile("mbarrier.init.shared.b64 [%0], %1;" :: "r"(addr), "r"(cnt) : "memory");
}
__device__ __forceinline__ void mbar_expect_tx(unsigned addr, unsigned bytes) {
    asm volatile("mbarrier.arrive.expect_tx.shared.b64 _, [%0], %1;"
                 :: "r"(addr), "r"(bytes) : "memory");
}
__device__ __forceinline__ void tma_bulk_g2s(unsigned dst, const void* src,
                                             unsigned bytes, unsigned mbar) {
    asm volatile("cp.async.bulk.shared::cta.global.mbarrier::complete_tx::bytes "
                 "[%0], [%1], %2, [%3];"
                 :: "r"(dst), "l"(src), "r"(bytes), "r"(mbar) : "memory");
}
__device__ __forceinline__ void mbar_wait(unsigned addr, unsigned parity) {
    unsigned done;
    asm volatile(
        "{\n\t.reg .pred p;\n\t"
        "mbarrier.try_wait.parity.acquire.cta.shared::cta.b64 p, [%1], %2;\n\t"
        "selp.b32 %0, 1, 0, p;\n\t}"
        : "=r"(done) : "r"(addr), "r"(parity) : "memory");
    if (!done) {
        asm volatile(
            "{\n\t.reg .pred P1;\n\t"
            "WL_%=:\n\t"
            "mbarrier.try_wait.parity.acquire.cta.shared::cta.b64 P1, [%0], %1, 0x989680;\n\t"
            "@P1 bra.uni WD_%=;\n\t"
            "bra.uni WL_%=;\n\t"
            "WD_%=:\n\t}"
            :: "r"(addr), "r"(parity) : "memory");
    }
}

__global__ __launch_bounds__(CTA_THREADS) void DownscaleLabel_kernel(
    const int* __restrict__ label, float* __restrict__ out)
{
    __shared__ alignas(128) uint8_t buf[2][16384];     // chunk ring (32 KB)
    __shared__ alignas(8)  unsigned long long mbar[2];
    __shared__ unsigned sm2[8][32][2];                 // [warp][tile-in-half][lo/hi]

    const int tid  = threadIdx.x;
    const int w    = tid >> 5;       // warp 0..7
    const int lane = tid & 31;
    const int h    = w >> 2;         // col half 0/1 (512 cols)
    const int r    = w & 3;          // row within chunk 0..3
    const int g    = lane >> 2;      // lane group 0..7

    const unsigned mb0 = smem_u32(&mbar[0]);
    const unsigned mb1 = smem_u32(&mbar[1]);
    const unsigned sb0 = smem_u32(&buf[0][0]);
    const unsigned sb1 = smem_u32(&buf[1][0]);

    if (tid == 0) { mbar_init(mb0, 1); mbar_init(mb1, 1); }
    __syncthreads();

    // Band source: 64 KB contiguous, blk = img*64 + band.
    const char* gsrc = (const char*)label + (size_t)blockIdx.x * 65536;

    if (tid == 0) {
        mbar_expect_tx(mb0, 16384); tma_bulk_g2s(sb0, gsrc,          16384u, mb0);
        mbar_expect_tx(mb1, 16384); tma_bulk_g2s(sb1, gsrc + 16384,  16384u, mb1);
    }

    // acc[cc]: byte-field histogram for sweep cc (classes 0..7, 8 bits each).
    // Per chunk adds <=4 per field, 4 chunks -> max 16. Fits.
    unsigned long long acc[4] = {0ull, 0ull, 0ull, 0ull};

    // Per-warp smem read base within a chunk: row r (4 KB), half h (2 KB).
    const uint8_t* rbase0 = &buf[0][0] + r * 4096 + h * 2048 + lane * 16;
    const uint8_t* rbase1 = &buf[1][0] + r * 4096 + h * 2048 + lane * 16;

    #pragma unroll
    for (int c = 0; c < 4; ++c) {
        mbar_wait((c & 1) ? mb1 : mb0, c >> 1);

        const uint8_t* rb = (c & 1) ? rbase1 : rbase0;
        #pragma unroll
        for (int cc = 0; cc < 4; ++cc) {
            int4 v = *reinterpret_cast<const int4*>(rb + cc * 512);
            int vals[4] = { v.x, v.y, v.z, v.w };
            #pragma unroll
            for (int k = 0; k < 4; ++k)
                acc[cc] += 1ull << (((unsigned)vals[k] & 7u) << 3);
        }

        if (c < 2) {
            __syncthreads();   // all warps done reading this buffer
            if (tid == 0) {
                const unsigned mb = (c & 1) ? mb1 : mb0;
                const unsigned sb = (c & 1) ? sb1 : sb0;
                mbar_expect_tx(mb, 16384);
                tma_bulk_g2s(sb, gsrc + (size_t)(c + 2) * 16384, 16384u, mb);
            }
        }
    }

    // Butterfly over the 4 lanes sharing tile (h*32 + cc*8 + g):
    // byte fields max 16 -> 32 -> 64, fits.
    #pragma unroll
    for (int cc = 0; cc < 4; ++cc) {
        unsigned lo = (unsigned)acc[cc];          // classes 0..3
        unsigned hi = (unsigned)(acc[cc] >> 32);  // classes 4..7
        lo += __shfl_xor_sync(0xFFFFFFFFu, lo, 1);
        hi += __shfl_xor_sync(0xFFFFFFFFu, hi, 1);
        lo += __shfl_xor_sync(0xFFFFFFFFu, lo, 2);
        hi += __shfl_xor_sync(0xFFFFFFFFu, hi, 2);
        if ((lane & 3) == 0) {
            sm2[w][cc * 8 + g][0] = lo;
            sm2[w][cc * 8 + g][1] = hi;
        }
    }

    __syncthreads();

    // 64 threads finalize 64 tiles: sum the 4 row-warps of each half,
    // expanding bytes -> halfwords (max 64*4 = 256, fits).
    if (tid < 64) {
        const int h2  = tid >> 5;    // col half
        const int idx = tid & 31;    // tile within half
        unsigned s0 = 0, s1 = 0, s2 = 0, s3 = 0;
        #pragma unroll
        for (int rr = 0; rr < 4; ++rr) {
            unsigned lo = sm2[h2 * 4 + rr][idx][0];
            unsigned hi = sm2[h2 * 4 + rr][idx][1];
            s0 += lo        & 0x00FF00FFu;   // classes 0, 2
            s1 += (lo >> 8) & 0x00FF00FFu;   // classes 1, 3
            s2 += hi        & 0x00FF00FFu;   // classes 4, 6
            s3 += (hi >> 8) & 0x00FF00FFu;   // classes 5, 7
        }
        int cnt[8];
        cnt[0] = (int)(s0 & 0xFFFFu); cnt[2] = (int)(s0 >> 16);
        cnt[1] = (int)(s1 & 0xFFFFu); cnt[3] = (int)(s1 >> 16);
        cnt[4] = (int)(s2 & 0xFFFFu); cnt[6] = (int)(s2 >> 16);
        cnt[5] = (int)(s3 & 0xFFFFu); cnt[7] = (int)(s3 >> 16);

        int best = cnt[0], bi = 0;
        #pragma unroll
        for (int c = 1; c < 8; ++c)
            if (cnt[c] > best) { best = cnt[c]; bi = c; }

        int res = (bi == 7 || best < 192) ? -1 : bi;   // 192/256 = 0.75 exact

        out[(size_t)blockIdx.x * 64 + tid] = (float)res;
    }
}

extern "C" void kernel_launch(void* const* d_in, const int* in_sizes, int n_in,
                              void* d_out, int out_size) {
    const int* label = (const int*)d_in[0];
    float* out = (float*)d_out;
    DownscaleLabel_kernel<<<512, CTA_THREADS>>>(label, out);
}